// round 1
// baseline (speedup 1.0000x reference)
#include <cuda_runtime.h>
#include <math.h>

#define BB 4
#define TT 2048
#define DD 512
#define HH 2048
#define VV 256
#define NTOK (BB*TT)   // 8192

// ---------------- scratch (device globals: allocation-free) ----------------
__device__ __align__(128) float g_h[NTOK*DD];     // residual stream
__device__ __align__(128) float g_s1[NTOK*DD];    // tanh(cumprod) / hcum / ctx
__device__ __align__(128) float g_s2[NTOK*DD];    // layernorm output
__device__ __align__(128) float g_act[NTOK*HH];   // GEMM1 activation
__device__ __align__(128) float g_mag[NTOK];

// ---------------- embedding gather ----------------
__global__ void embed_kernel(const int* __restrict__ x, const float* __restrict__ embed) {
    int i = blockIdx.x * blockDim.x + threadIdx.x;  // over NTOK*DD
    int tok = i >> 9;
    int d = i & (DD - 1);
    g_h[i] = embed[x[tok] * DD + d];
}

// ---------------- tanh(cumprod over feature dim) ----------------
__global__ void cumprod_tanh_kernel() {
    __shared__ float s[DD];
    int tok = blockIdx.x;
    int d = threadIdx.x;
    size_t base = (size_t)tok * DD;
    s[d] = g_h[base + d];
    __syncthreads();
    #pragma unroll
    for (int off = 1; off < DD; off <<= 1) {
        float t = (d >= off) ? s[d - off] : 1.0f;
        __syncthreads();
        s[d] *= t;
        __syncthreads();
    }
    g_s1[base + d] = tanhf(s[d]);
}

// ---------------- bd = cumsum_t(g); h = h*(1+bd) ----------------
__global__ void boundary_kernel() {
    int b = blockIdx.x;
    int d = threadIdx.x;
    size_t base = (size_t)b * TT * DD + d;
    float acc = 0.f;
    for (int t0 = 0; t0 < TT; t0 += 8) {
        float gv[8], hv[8];
        #pragma unroll
        for (int i = 0; i < 8; i++) {
            size_t idx = base + (size_t)(t0 + i) * DD;
            gv[i] = g_s1[idx];
            hv[i] = g_h[idx];
        }
        #pragma unroll
        for (int i = 0; i < 8; i++) {
            acc += gv[i];
            g_h[base + (size_t)(t0 + i) * DD] = hv[i] * (1.0f + acc);
        }
    }
}

// ---------------- hcum = cumsum_t(h) -> s1 ----------------
__global__ void cumsum_h_kernel() {
    int b = blockIdx.x;
    int d = threadIdx.x;
    size_t base = (size_t)b * TT * DD + d;
    float acc = 0.f;
    for (int t0 = 0; t0 < TT; t0 += 8) {
        float hv[8];
        #pragma unroll
        for (int i = 0; i < 8; i++) hv[i] = g_h[base + (size_t)(t0 + i) * DD];
        #pragma unroll
        for (int i = 0; i < 8; i++) {
            acc += hv[i];
            g_s1[base + (size_t)(t0 + i) * DD] = acc;
        }
    }
}

// ---------------- block reduction helper ----------------
__device__ __forceinline__ float block_reduce(float v, float* sh) {
    int lane = threadIdx.x & 31, wid = threadIdx.x >> 5;
    #pragma unroll
    for (int o = 16; o; o >>= 1) v += __shfl_down_sync(0xffffffffu, v, o);
    if (lane == 0) sh[wid] = v;
    __syncthreads();
    float r = 0.f;
    if (threadIdx.x < (blockDim.x >> 5)) r = sh[threadIdx.x];
    if (wid == 0) {
        #pragma unroll
        for (int o = 16; o; o >>= 1) r += __shfl_down_sync(0xffffffffu, r, o);
        if (lane == 0) sh[0] = r;
    }
    __syncthreads();
    r = sh[0];
    __syncthreads();
    return r;
}

// ---------------- mag[b,t] = ||hcum[b,t] - h[b,t-1]|| ----------------
__global__ void mag_kernel() {
    __shared__ float sh[32];
    int tok = blockIdx.x;
    int t = tok & (TT - 1);
    size_t base = (size_t)tok * DD;
    float s = 0.f;
    for (int d = threadIdx.x; d < DD; d += blockDim.x) {
        float prev = (t > 0) ? g_h[base - DD + d] : 0.f;
        float diff = g_s1[base + d] - prev;
        s += diff * diff;
    }
    s = block_reduce(s, sh);
    if (threadIdx.x == 0) g_mag[tok] = sqrtf(s);
}

// ---------------- ctx = |mag * decay-scan(h)| -> s1 ----------------
__global__ void decay_ctx_kernel(const float* __restrict__ kpar, int l) {
    int b = blockIdx.x;
    int d = threadIdx.x;
    float kv = kpar[l];
    float sp = (kv > 0.f) ? (kv + log1pf(expf(-kv))) : log1pf(expf(kv));
    float lam = expf(-sp);
    size_t base = (size_t)b * TT * DD + d;
    float S = 0.f;
    for (int t0 = 0; t0 < TT; t0 += 8) {
        float hv[8], mv[8];
        #pragma unroll
        for (int i = 0; i < 8; i++) {
            hv[i] = g_h[base + (size_t)(t0 + i) * DD];
            mv[i] = g_mag[b * TT + t0 + i];
        }
        #pragma unroll
        for (int i = 0; i < 8; i++) {
            S = hv[i] + lam * S;
            g_s1[base + (size_t)(t0 + i) * DD] = fabsf(mv[i] * S);
        }
    }
}

// ---------------- layernorm(ctx) -> s2  (eps = 1e-3) ----------------
__global__ void layernorm_kernel(const float* __restrict__ gamma, const float* __restrict__ beta) {
    __shared__ float row[DD];
    __shared__ float sh[32];
    int tok = blockIdx.x;
    size_t base = (size_t)tok * DD;
    float s = 0.f;
    for (int d = threadIdx.x; d < DD; d += blockDim.x) {
        float v = g_s1[base + d];
        row[d] = v;
        s += v;
    }
    s = block_reduce(s, sh);
    float mu = s * (1.0f / DD);
    float q = 0.f;
    for (int d = threadIdx.x; d < DD; d += blockDim.x) {
        float v = row[d] - mu;
        q += v * v;
    }
    q = block_reduce(q, sh);
    float rstd = rsqrtf(q * (1.0f / DD) + 1e-3f);
    for (int d = threadIdx.x; d < DD; d += blockDim.x) {
        g_s2[base + d] = (row[d] - mu) * rstd * gamma[d] + beta[d];
    }
}

// ---------------- tiled SGEMM core: 128x128x16, 8x8/thread, 256 threads ----
// EPI: 0 = bias+GELU(store), 1 = bias + accumulate into C, 2 = plain store
// BT:  false -> B is [K,N] row-major; true -> B is [N,K] row-major (B^T)
template <int EPI, bool BT>
__device__ __forceinline__ void gemm_core(const float* __restrict__ A,
                                          const float* __restrict__ B,
                                          const float* __restrict__ bias,
                                          float* __restrict__ C,
                                          int M, int N, int K) {
    __shared__ float As[16][128];
    __shared__ float Bs[16][132];
    const int bm = blockIdx.y * 128, bn = blockIdx.x * 128;
    const int tid = threadIdx.x;
    const int ty = tid >> 4, tx = tid & 15;
    float acc[8][8];
    #pragma unroll
    for (int i = 0; i < 8; i++)
        #pragma unroll
        for (int j = 0; j < 8; j++) acc[i][j] = 0.f;

    for (int k0 = 0; k0 < K; k0 += 16) {
        #pragma unroll
        for (int r = 0; r < 2; r++) {
            int slot = tid + r * 256;            // 512 float4 slots: 128 rows x 4
            int arow = slot >> 2;
            int ac = (slot & 3) << 2;
            const float4 v = *(const float4*)(A + (size_t)(bm + arow) * K + k0 + ac);
            As[ac + 0][arow] = v.x;
            As[ac + 1][arow] = v.y;
            As[ac + 2][arow] = v.z;
            As[ac + 3][arow] = v.w;
        }
        if (!BT) {
            #pragma unroll
            for (int r = 0; r < 2; r++) {
                int slot = tid + r * 256;        // 16 rows x 32 float4
                int br = slot >> 5;
                int bc = (slot & 31) << 2;
                *(float4*)(&Bs[br][bc]) = *(const float4*)(B + (size_t)(k0 + br) * N + bn + bc);
            }
        } else {
            #pragma unroll
            for (int r = 0; r < 2; r++) {
                int slot = tid + r * 256;        // 128 n-rows x 4 float4 along K
                int nr = slot >> 2;
                int kc = (slot & 3) << 2;
                const float4 v = *(const float4*)(B + (size_t)(bn + nr) * K + k0 + kc);
                Bs[kc + 0][nr] = v.x;
                Bs[kc + 1][nr] = v.y;
                Bs[kc + 2][nr] = v.z;
                Bs[kc + 3][nr] = v.w;
            }
        }
        __syncthreads();
        #pragma unroll
        for (int kk = 0; kk < 16; kk++) {
            float ra[8], rb[8];
            *(float4*)&ra[0] = *(const float4*)&As[kk][ty * 8];
            *(float4*)&ra[4] = *(const float4*)&As[kk][ty * 8 + 4];
            *(float4*)&rb[0] = *(const float4*)&Bs[kk][tx * 8];
            *(float4*)&rb[4] = *(const float4*)&Bs[kk][tx * 8 + 4];
            #pragma unroll
            for (int i = 0; i < 8; i++)
                #pragma unroll
                for (int j = 0; j < 8; j++) acc[i][j] += ra[i] * rb[j];
        }
        __syncthreads();
    }

    int row0 = bm + ty * 8, col0 = bn + tx * 8;
    #pragma unroll
    for (int i = 0; i < 8; i++) {
        #pragma unroll
        for (int j = 0; j < 8; j++) {
            float c = acc[i][j];
            if (EPI != 2) c += bias[col0 + j];
            size_t idx = (size_t)(row0 + i) * N + col0 + j;
            if (EPI == 0) {
                C[idx] = 0.5f * c * (1.0f + erff(c * 0.70710678118654752f));  // exact GELU
            } else if (EPI == 1) {
                C[idx] += c;
            } else {
                C[idx] = c;
            }
        }
    }
}

__global__ void __launch_bounds__(256) gemm1_kernel(const float* __restrict__ W1,
                                                    const float* __restrict__ b1) {
    gemm_core<0, false>(g_s2, W1, b1, g_act, NTOK, HH, DD);
}
__global__ void __launch_bounds__(256) gemm2_kernel(const float* __restrict__ W2,
                                                    const float* __restrict__ b2) {
    gemm_core<1, false>(g_act, W2, b2, g_h, NTOK, DD, HH);
}
__global__ void __launch_bounds__(256) gemm_out_kernel(const float* __restrict__ embed,
                                                       float* __restrict__ out) {
    gemm_core<2, true>(g_h, embed, nullptr, out, NTOK, VV, DD);
}

// ---------------- launcher ----------------
extern "C" void kernel_launch(void* const* d_in, const int* in_sizes, int n_in,
                              void* d_out, int out_size) {
    const int*   x     = (const int*)d_in[0];
    const float* embed = (const float*)d_in[1];
    const float* kpar  = (const float*)d_in[2];
    const float* gamma = (const float*)d_in[3];
    const float* beta  = (const float*)d_in[4];
    const float* W1    = (const float*)d_in[5];
    const float* b1    = (const float*)d_in[6];
    const float* W2    = (const float*)d_in[7];
    const float* b2    = (const float*)d_in[8];
    float* out = (float*)d_out;

    embed_kernel<<<(NTOK * DD) / 256, 256>>>(x, embed);
    cumprod_tanh_kernel<<<NTOK, DD>>>();
    boundary_kernel<<<BB, DD>>>();

    for (int l = 0; l < 3; l++) {
        cumsum_h_kernel<<<BB, DD>>>();
        mag_kernel<<<NTOK, 256>>>();
        decay_ctx_kernel<<<BB, DD>>>(kpar, l);
        layernorm_kernel<<<NTOK, 128>>>(gamma + l * DD, beta + l * DD);
        gemm1_kernel<<<dim3(HH / 128, NTOK / 128), 256>>>(W1 + (size_t)l * DD * HH, b1 + l * HH);
        gemm2_kernel<<<dim3(DD / 128, NTOK / 128), 256>>>(W2 + (size_t)l * HH * DD, b2 + l * DD);
    }
    gemm_out_kernel<<<dim3(VV / 128, NTOK / 128), 256>>>(embed, out);
}

// round 2
// speedup vs baseline: 1.2096x; 1.2096x over previous
#include <cuda_runtime.h>
#include <math.h>

#define BB 4
#define TT 2048
#define DD 512
#define HH 2048
#define VV 256
#define NTOK (BB*TT)   // 8192
#define CS 64          // scan chunk length (time steps)
#define NCH (TT/CS)    // 32 chunks -> 4*32 = 128 blocks per scan pass

// ---------------- scratch (device globals: allocation-free) ----------------
__device__ __align__(128) float g_h[NTOK*DD];     // residual stream
__device__ __align__(128) float g_s1[NTOK*DD];    // tanh(cumprod) / ctx
__device__ __align__(128) float g_s2[NTOK*DD];    // layernorm output
__device__ __align__(128) float g_act[NTOK*HH];   // GEMM1 activation
__device__ __align__(128) float g_mag[NTOK];
__device__ __align__(128) float g_partA[BB*NCH*DD];  // cumsum chunk partials/carries
__device__ __align__(128) float g_partB[BB*NCH*DD];  // decay chunk partials/carries

__device__ __forceinline__ float softplus_lambda(float kv) {
    float sp = (kv > 0.f) ? (kv + log1pf(expf(-kv))) : log1pf(expf(kv));
    return expf(-sp);
}

// ---------------- embedding gather ----------------
__global__ void embed_kernel(const int* __restrict__ x, const float* __restrict__ embed) {
    int i = blockIdx.x * blockDim.x + threadIdx.x;  // over NTOK*DD
    int tok = i >> 9;
    int d = i & (DD - 1);
    g_h[i] = embed[x[tok] * DD + d];
}

// ---------------- tanh(cumprod over feature dim) -> s1 ----------------
__global__ void cumprod_tanh_kernel() {
    __shared__ float s[DD];
    int tok = blockIdx.x;
    int d = threadIdx.x;
    size_t base = (size_t)tok * DD;
    s[d] = g_h[base + d];
    __syncthreads();
    #pragma unroll
    for (int off = 1; off < DD; off <<= 1) {
        float t = (d >= off) ? s[d - off] : 1.0f;
        __syncthreads();
        s[d] *= t;
        __syncthreads();
    }
    g_s1[base + d] = tanhf(s[d]);
}

// ============= boundary: bd = cumsum_t(s1); h = h*(1+bd) — 3-pass scan =====
__global__ void boundA_kernel() {           // chunk sums of s1
    int b = blockIdx.x, ch = blockIdx.y, d = threadIdx.x;
    size_t base = ((size_t)b * TT + ch * CS) * DD + d;
    float s = 0.f;
    #pragma unroll 8
    for (int i = 0; i < CS; i++) s += g_s1[base + (size_t)i * DD];
    g_partA[((size_t)b * NCH + ch) * DD + d] = s;
}

__global__ void boundB_kernel() {           // exclusive scan over chunks
    int b = blockIdx.x, d = threadIdx.x;
    float c = 0.f;
    for (int ch = 0; ch < NCH; ch++) {
        size_t idx = ((size_t)b * NCH + ch) * DD + d;
        float v = g_partA[idx];
        g_partA[idx] = c;
        c += v;
    }
}

__global__ void boundC_kernel() {           // apply: h = h*(1+cumsum)
    int b = blockIdx.x, ch = blockIdx.y, d = threadIdx.x;
    size_t base = ((size_t)b * TT + ch * CS) * DD + d;
    float acc = g_partA[((size_t)b * NCH + ch) * DD + d];
    #pragma unroll 4
    for (int i = 0; i < CS; i++) {
        size_t idx = base + (size_t)i * DD;
        acc += g_s1[idx];
        g_h[idx] = g_h[idx] * (1.0f + acc);
    }
}

// ============= per-layer pass A: chunk cumsum partial + decay-local =======
__global__ void scanA_kernel(const float* __restrict__ kpar, int l) {
    int b = blockIdx.x, ch = blockIdx.y, d = threadIdx.x;
    float lam = softplus_lambda(kpar[l]);
    size_t base = ((size_t)b * TT + ch * CS) * DD + d;
    float s = 0.f, loc = 0.f;
    #pragma unroll 4
    for (int i = 0; i < CS; i++) {
        float v = g_h[base + (size_t)i * DD];
        s += v;
        loc = v + lam * loc;
    }
    size_t pidx = ((size_t)b * NCH + ch) * DD + d;
    g_partA[pidx] = s;
    g_partB[pidx] = loc;
}

// ============= per-layer pass B: carries for both scans ====================
__global__ void scanB_kernel(const float* __restrict__ kpar, int l) {
    int b = blockIdx.x, d = threadIdx.x;
    float lam = softplus_lambda(kpar[l]);
    float lamCS = powf(lam, (float)CS);
    float c1 = 0.f, c2 = 0.f;
    for (int ch = 0; ch < NCH; ch++) {
        size_t idx = ((size_t)b * NCH + ch) * DD + d;
        float a = g_partA[idx];
        float v = g_partB[idx];
        g_partA[idx] = c1;          // exclusive cumsum carry
        g_partB[idx] = c2;          // decay carry-in (S at end of prev chunk)
        c1 += a;
        c2 = v + lamCS * c2;
    }
}

// ============= per-layer pass C1: mag (hcum never materialized) ============
__global__ void magC_kernel() {
    __shared__ float accw[CS][17];
    int b = blockIdx.x, ch = blockIdx.y;
    int d = threadIdx.x;
    int lane = d & 31, wid = d >> 5;    // 16 warps
    int t0 = ch * CS;
    size_t base = ((size_t)b * TT + t0) * DD + d;
    float acc = g_partA[((size_t)b * NCH + ch) * DD + d];
    float hp = (t0 > 0) ? g_h[base - DD] : 0.f;
    #pragma unroll 4
    for (int i = 0; i < CS; i++) {
        float v = g_h[base + (size_t)i * DD];
        acc += v;                        // hcum[t, d]
        float diff = acc - hp;
        float sq = diff * diff;
        #pragma unroll
        for (int o = 16; o; o >>= 1) sq += __shfl_down_sync(0xffffffffu, sq, o);
        if (lane == 0) accw[i][wid] = sq;
        hp = v;
    }
    __syncthreads();
    if (d < CS) {
        float s = 0.f;
        #pragma unroll
        for (int w = 0; w < 16; w++) s += accw[d][w];
        g_mag[b * TT + t0 + d] = sqrtf(s);
    }
}

// ============= per-layer pass C2: ctx = |mag * decay-scan(h)| -> s1 ========
__global__ void decayC_kernel(const float* __restrict__ kpar, int l) {
    int b = blockIdx.x, ch = blockIdx.y, d = threadIdx.x;
    float lam = softplus_lambda(kpar[l]);
    int t0 = ch * CS;
    size_t base = ((size_t)b * TT + t0) * DD + d;
    float S = g_partB[((size_t)b * NCH + ch) * DD + d];
    #pragma unroll 4
    for (int i = 0; i < CS; i++) {
        size_t idx = base + (size_t)i * DD;
        S = g_h[idx] + lam * S;
        g_s1[idx] = fabsf(g_mag[b * TT + t0 + i] * S);
    }
}

// ---------------- block reduction helper ----------------
__device__ __forceinline__ float block_reduce(float v, float* sh) {
    int lane = threadIdx.x & 31, wid = threadIdx.x >> 5;
    #pragma unroll
    for (int o = 16; o; o >>= 1) v += __shfl_down_sync(0xffffffffu, v, o);
    if (lane == 0) sh[wid] = v;
    __syncthreads();
    float r = 0.f;
    if (threadIdx.x < (blockDim.x >> 5)) r = sh[threadIdx.x];
    if (wid == 0) {
        #pragma unroll
        for (int o = 16; o; o >>= 1) r += __shfl_down_sync(0xffffffffu, r, o);
        if (lane == 0) sh[0] = r;
    }
    __syncthreads();
    r = sh[0];
    __syncthreads();
    return r;
}

// ---------------- layernorm(ctx) -> s2  (eps = 1e-3) ----------------
__global__ void layernorm_kernel(const float* __restrict__ gamma, const float* __restrict__ beta) {
    __shared__ float row[DD];
    __shared__ float sh[32];
    int tok = blockIdx.x;
    size_t base = (size_t)tok * DD;
    float s = 0.f;
    for (int d = threadIdx.x; d < DD; d += blockDim.x) {
        float v = g_s1[base + d];
        row[d] = v;
        s += v;
    }
    s = block_reduce(s, sh);
    float mu = s * (1.0f / DD);
    float q = 0.f;
    for (int d = threadIdx.x; d < DD; d += blockDim.x) {
        float v = row[d] - mu;
        q += v * v;
    }
    q = block_reduce(q, sh);
    float rstd = rsqrtf(q * (1.0f / DD) + 1e-3f);
    for (int d = threadIdx.x; d < DD; d += blockDim.x) {
        g_s2[base + d] = (row[d] - mu) * rstd * gamma[d] + beta[d];
    }
}

// ---------------- tiled SGEMM core: 128x128x16, 8x8/thread, 256 threads ----
// EPI: 0 = bias+GELU(store), 1 = bias + accumulate into C, 2 = plain store
// BT:  false -> B is [K,N] row-major; true -> B is [N,K] row-major (B^T)
template <int EPI, bool BT>
__device__ __forceinline__ void gemm_core(const float* __restrict__ A,
                                          const float* __restrict__ B,
                                          const float* __restrict__ bias,
                                          float* __restrict__ C,
                                          int M, int N, int K) {
    __shared__ float As[16][128];
    __shared__ float Bs[16][132];
    const int bm = blockIdx.y * 128, bn = blockIdx.x * 128;
    const int tid = threadIdx.x;
    const int ty = tid >> 4, tx = tid & 15;
    float acc[8][8];
    #pragma unroll
    for (int i = 0; i < 8; i++)
        #pragma unroll
        for (int j = 0; j < 8; j++) acc[i][j] = 0.f;

    for (int k0 = 0; k0 < K; k0 += 16) {
        #pragma unroll
        for (int r = 0; r < 2; r++) {
            int slot = tid + r * 256;            // 512 float4 slots: 128 rows x 4
            int arow = slot >> 2;
            int ac = (slot & 3) << 2;
            const float4 v = *(const float4*)(A + (size_t)(bm + arow) * K + k0 + ac);
            As[ac + 0][arow] = v.x;
            As[ac + 1][arow] = v.y;
            As[ac + 2][arow] = v.z;
            As[ac + 3][arow] = v.w;
        }
        if (!BT) {
            #pragma unroll
            for (int r = 0; r < 2; r++) {
                int slot = tid + r * 256;        // 16 rows x 32 float4
                int br = slot >> 5;
                int bc = (slot & 31) << 2;
                *(float4*)(&Bs[br][bc]) = *(const float4*)(B + (size_t)(k0 + br) * N + bn + bc);
            }
        } else {
            #pragma unroll
            for (int r = 0; r < 2; r++) {
                int slot = tid + r * 256;        // 128 n-rows x 4 float4 along K
                int nr = slot >> 2;
                int kc = (slot & 3) << 2;
                const float4 v = *(const float4*)(B + (size_t)(bn + nr) * K + k0 + kc);
                Bs[kc + 0][nr] = v.x;
                Bs[kc + 1][nr] = v.y;
                Bs[kc + 2][nr] = v.z;
                Bs[kc + 3][nr] = v.w;
            }
        }
        __syncthreads();
        #pragma unroll
        for (int kk = 0; kk < 16; kk++) {
            float ra[8], rb[8];
            *(float4*)&ra[0] = *(const float4*)&As[kk][ty * 8];
            *(float4*)&ra[4] = *(const float4*)&As[kk][ty * 8 + 4];
            *(float4*)&rb[0] = *(const float4*)&Bs[kk][tx * 8];
            *(float4*)&rb[4] = *(const float4*)&Bs[kk][tx * 8 + 4];
            #pragma unroll
            for (int i = 0; i < 8; i++)
                #pragma unroll
                for (int j = 0; j < 8; j++) acc[i][j] += ra[i] * rb[j];
        }
        __syncthreads();
    }

    int row0 = bm + ty * 8, col0 = bn + tx * 8;
    #pragma unroll
    for (int i = 0; i < 8; i++) {
        #pragma unroll
        for (int j = 0; j < 8; j++) {
            float c = acc[i][j];
            if (EPI != 2) c += bias[col0 + j];
            size_t idx = (size_t)(row0 + i) * N + col0 + j;
            if (EPI == 0) {
                C[idx] = 0.5f * c * (1.0f + erff(c * 0.70710678118654752f));  // exact GELU
            } else if (EPI == 1) {
                C[idx] += c;
            } else {
                C[idx] = c;
            }
        }
    }
}

__global__ void __launch_bounds__(256) gemm1_kernel(const float* __restrict__ W1,
                                                    const float* __restrict__ b1) {
    gemm_core<0, false>(g_s2, W1, b1, g_act, NTOK, HH, DD);
}
__global__ void __launch_bounds__(256) gemm2_kernel(const float* __restrict__ W2,
                                                    const float* __restrict__ b2) {
    gemm_core<1, false>(g_act, W2, b2, g_h, NTOK, DD, HH);
}
__global__ void __launch_bounds__(256) gemm_out_kernel(const float* __restrict__ embed,
                                                       float* __restrict__ out) {
    gemm_core<2, true>(g_h, embed, nullptr, out, NTOK, VV, DD);
}

// ---------------- launcher ----------------
extern "C" void kernel_launch(void* const* d_in, const int* in_sizes, int n_in,
                              void* d_out, int out_size) {
    const int*   x     = (const int*)d_in[0];
    const float* embed = (const float*)d_in[1];
    const float* kpar  = (const float*)d_in[2];
    const float* gamma = (const float*)d_in[3];
    const float* beta  = (const float*)d_in[4];
    const float* W1    = (const float*)d_in[5];
    const float* b1    = (const float*)d_in[6];
    const float* W2    = (const float*)d_in[7];
    const float* b2    = (const float*)d_in[8];
    float* out = (float*)d_out;

    dim3 sg(BB, NCH);

    embed_kernel<<<(NTOK * DD) / 256, 256>>>(x, embed);
    cumprod_tanh_kernel<<<NTOK, DD>>>();
    boundA_kernel<<<sg, DD>>>();
    boundB_kernel<<<BB, DD>>>();
    boundC_kernel<<<sg, DD>>>();

    for (int l = 0; l < 3; l++) {
        scanA_kernel<<<sg, DD>>>(kpar, l);
        scanB_kernel<<<BB, DD>>>(kpar, l);
        magC_kernel<<<sg, DD>>>();
        decayC_kernel<<<sg, DD>>>(kpar, l);
        layernorm_kernel<<<NTOK, 128>>>(gamma + l * DD, beta + l * DD);
        gemm1_kernel<<<dim3(HH / 128, NTOK / 128), 256>>>(W1 + (size_t)l * DD * HH, b1 + l * HH);
        gemm2_kernel<<<dim3(DD / 128, NTOK / 128), 256>>>(W2 + (size_t)l * HH * DD, b2 + l * DD);
    }
    gemm_out_kernel<<<dim3(VV / 128, NTOK / 128), 256>>>(embed, out);
}

// round 3
// speedup vs baseline: 1.5021x; 1.2418x over previous
#include <cuda_runtime.h>
#include <math.h>
#include <stdint.h>

#define BB 4
#define TT 2048
#define DD 512
#define HH 2048
#define VV 256
#define NTOK (BB*TT)   // 8192
#define CS 64          // scan chunk length (time steps)
#define NCH (TT/CS)    // 32 chunks -> 4*32 = 128 blocks per scan pass

// ---------------- scratch (device globals: allocation-free) ----------------
__device__ __align__(128) float g_h[NTOK*DD];     // residual stream
__device__ __align__(128) float g_s1[NTOK*DD];    // tanh(cumprod) / ctx
__device__ __align__(128) float g_s2[NTOK*DD];    // layernorm output
__device__ __align__(128) float g_act[NTOK*HH];   // GEMM1 activation
__device__ __align__(128) float g_mag[NTOK];
__device__ __align__(128) float g_partA[BB*NCH*DD];
__device__ __align__(128) float g_partB[BB*NCH*DD];

__device__ __forceinline__ float softplus_lambda(float kv) {
    float sp = (kv > 0.f) ? (kv + log1pf(expf(-kv))) : log1pf(expf(kv));
    return expf(-sp);
}

// ---------------- embedding gather ----------------
__global__ void embed_kernel(const int* __restrict__ x, const float* __restrict__ embed) {
    int i = blockIdx.x * blockDim.x + threadIdx.x;
    int tok = i >> 9;
    int d = i & (DD - 1);
    g_h[i] = embed[x[tok] * DD + d];
}

// ---------------- tanh(cumprod over feature dim) -> s1 ----------------
__global__ void cumprod_tanh_kernel() {
    __shared__ float s[DD];
    int tok = blockIdx.x;
    int d = threadIdx.x;
    size_t base = (size_t)tok * DD;
    s[d] = g_h[base + d];
    __syncthreads();
    #pragma unroll
    for (int off = 1; off < DD; off <<= 1) {
        float t = (d >= off) ? s[d - off] : 1.0f;
        __syncthreads();
        s[d] *= t;
        __syncthreads();
    }
    g_s1[base + d] = tanhf(s[d]);
}

// ============= boundary scan ================================================
__global__ void boundA_kernel() {
    int b = blockIdx.x, ch = blockIdx.y, d = threadIdx.x;
    size_t base = ((size_t)b * TT + ch * CS) * DD + d;
    float s = 0.f;
    #pragma unroll 8
    for (int i = 0; i < CS; i++) s += g_s1[base + (size_t)i * DD];
    g_partA[((size_t)b * NCH + ch) * DD + d] = s;
}

__global__ void boundB_kernel() {
    int b = blockIdx.x, d = threadIdx.x;
    float c = 0.f;
    for (int ch = 0; ch < NCH; ch++) {
        size_t idx = ((size_t)b * NCH + ch) * DD + d;
        float v = g_partA[idx];
        g_partA[idx] = c;
        c += v;
    }
}

__global__ void boundC_kernel() {
    int b = blockIdx.x, ch = blockIdx.y, d = threadIdx.x;
    size_t base = ((size_t)b * TT + ch * CS) * DD + d;
    float acc = g_partA[((size_t)b * NCH + ch) * DD + d];
    #pragma unroll 4
    for (int i = 0; i < CS; i++) {
        size_t idx = base + (size_t)i * DD;
        acc += g_s1[idx];
        g_h[idx] = g_h[idx] * (1.0f + acc);
    }
}

// ============= per-layer scans =============================================
__global__ void scanA_kernel(const float* __restrict__ kpar, int l) {
    int b = blockIdx.x, ch = blockIdx.y, d = threadIdx.x;
    float lam = softplus_lambda(kpar[l]);
    size_t base = ((size_t)b * TT + ch * CS) * DD + d;
    float s = 0.f, loc = 0.f;
    #pragma unroll 4
    for (int i = 0; i < CS; i++) {
        float v = g_h[base + (size_t)i * DD];
        s += v;
        loc = v + lam * loc;
    }
    size_t pidx = ((size_t)b * NCH + ch) * DD + d;
    g_partA[pidx] = s;
    g_partB[pidx] = loc;
}

__global__ void scanB_kernel(const float* __restrict__ kpar, int l) {
    int b = blockIdx.x, d = threadIdx.x;
    float lam = softplus_lambda(kpar[l]);
    float lamCS = powf(lam, (float)CS);
    float c1 = 0.f, c2 = 0.f;
    for (int ch = 0; ch < NCH; ch++) {
        size_t idx = ((size_t)b * NCH + ch) * DD + d;
        float a = g_partA[idx];
        float v = g_partB[idx];
        g_partA[idx] = c1;
        g_partB[idx] = c2;
        c1 += a;
        c2 = v + lamCS * c2;
    }
}

__global__ void magC_kernel() {
    __shared__ float accw[CS][17];
    int b = blockIdx.x, ch = blockIdx.y;
    int d = threadIdx.x;
    int lane = d & 31, wid = d >> 5;
    int t0 = ch * CS;
    size_t base = ((size_t)b * TT + t0) * DD + d;
    float acc = g_partA[((size_t)b * NCH + ch) * DD + d];
    float hp = (t0 > 0) ? g_h[base - DD] : 0.f;
    #pragma unroll 4
    for (int i = 0; i < CS; i++) {
        float v = g_h[base + (size_t)i * DD];
        acc += v;
        float diff = acc - hp;
        float sq = diff * diff;
        #pragma unroll
        for (int o = 16; o; o >>= 1) sq += __shfl_down_sync(0xffffffffu, sq, o);
        if (lane == 0) accw[i][wid] = sq;
        hp = v;
    }
    __syncthreads();
    if (d < CS) {
        float s = 0.f;
        #pragma unroll
        for (int w = 0; w < 16; w++) s += accw[d][w];
        g_mag[b * TT + t0 + d] = sqrtf(s);
    }
}

__global__ void decayC_kernel(const float* __restrict__ kpar, int l) {
    int b = blockIdx.x, ch = blockIdx.y, d = threadIdx.x;
    float lam = softplus_lambda(kpar[l]);
    int t0 = ch * CS;
    size_t base = ((size_t)b * TT + t0) * DD + d;
    float S = g_partB[((size_t)b * NCH + ch) * DD + d];
    #pragma unroll 4
    for (int i = 0; i < CS; i++) {
        size_t idx = base + (size_t)i * DD;
        S = g_h[idx] + lam * S;
        g_s1[idx] = fabsf(g_mag[b * TT + t0 + i] * S);
    }
}

// ---------------- block reduction helper ----------------
__device__ __forceinline__ float block_reduce(float v, float* sh) {
    int lane = threadIdx.x & 31, wid = threadIdx.x >> 5;
    #pragma unroll
    for (int o = 16; o; o >>= 1) v += __shfl_down_sync(0xffffffffu, v, o);
    if (lane == 0) sh[wid] = v;
    __syncthreads();
    float r = 0.f;
    if (threadIdx.x < (blockDim.x >> 5)) r = sh[threadIdx.x];
    if (wid == 0) {
        #pragma unroll
        for (int o = 16; o; o >>= 1) r += __shfl_down_sync(0xffffffffu, r, o);
        if (lane == 0) sh[0] = r;
    }
    __syncthreads();
    r = sh[0];
    __syncthreads();
    return r;
}

// ---------------- layernorm(ctx) -> s2  (eps = 1e-3) ----------------
__global__ void layernorm_kernel(const float* __restrict__ gamma, const float* __restrict__ beta) {
    __shared__ float row[DD];
    __shared__ float sh[32];
    int tok = blockIdx.x;
    size_t base = (size_t)tok * DD;
    float s = 0.f;
    for (int d = threadIdx.x; d < DD; d += blockDim.x) {
        float v = g_s1[base + d];
        row[d] = v;
        s += v;
    }
    s = block_reduce(s, sh);
    float mu = s * (1.0f / DD);
    float q = 0.f;
    for (int d = threadIdx.x; d < DD; d += blockDim.x) {
        float v = row[d] - mu;
        q += v * v;
    }
    q = block_reduce(q, sh);
    float rstd = rsqrtf(q * (1.0f / DD) + 1e-3f);
    for (int d = threadIdx.x; d < DD; d += blockDim.x) {
        g_s2[base + d] = (row[d] - mu) * rstd * gamma[d] + beta[d];
    }
}

// ================= TF32x3 tensor-core GEMM =================================
// C[M,N] = A[M,K] @ B[K,N], split-TF32 (3 mma terms), fp32 accum.
// Block tile 128x256x16, 8 warps (2m x 4n), warp tile 64x64.
// EPI: 0 = bias+GELU store, 1 = bias + accumulate into C.

#define ASTRIDE 20     // words per A smem row (conflict-free, 16B aligned)
#define BSTRIDE 264    // words per B smem row (conflict-free, 16B aligned)
#define A_BUF (128*ASTRIDE)
#define B_BUF (16*BSTRIDE)
#define GSMEM_BYTES ((2*A_BUF*2 + 2*B_BUF*2) * 4)   // hi/lo, double buffered

__device__ __forceinline__ uint32_t f2tf(float x) {
    uint32_t r;
    asm("cvt.rna.tf32.f32 %0, %1;" : "=r"(r) : "f"(x));
    return r;
}

#define MMA_TF32(c, a, b0, b1)                                                  \
    asm volatile("mma.sync.aligned.m16n8k8.row.col.f32.tf32.tf32.f32 "          \
                 "{%0,%1,%2,%3},{%4,%5,%6,%7},{%8,%9},{%0,%1,%2,%3};"           \
                 : "+f"(c[0]), "+f"(c[1]), "+f"(c[2]), "+f"(c[3])               \
                 : "r"(a[0]), "r"(a[1]), "r"(a[2]), "r"(a[3]), "r"(b0), "r"(b1))

template <int EPI>
__device__ __forceinline__ void gemm_tf32_core(const float* __restrict__ A,
                                               const float* __restrict__ B,
                                               const float* __restrict__ bias,
                                               float* __restrict__ C,
                                               int M, int N, int K) {
    extern __shared__ uint32_t sm[];
    uint32_t* sAh = sm;
    uint32_t* sAl = sAh + 2 * A_BUF;
    uint32_t* sBh = sAl + 2 * A_BUF;
    uint32_t* sBl = sBh + 2 * B_BUF;

    const int bm = blockIdx.y * 128;
    const int bn = blockIdx.x * 256;
    const int tid = threadIdx.x;
    const int lane = tid & 31;
    const int wid = tid >> 5;
    const int wm = wid >> 2;      // 0..1
    const int wn = wid & 3;       // 0..3
    const int g = lane >> 2;      // 0..7
    const int kq = lane & 3;      // 0..3

    // staging slot mapping
    const int arow = tid >> 2;          // slots tid, tid+256 -> rows via slot>>2
    const int ac4 = tid & 3;
    const int bn4 = tid & 63;           // slot&63

    float acc[4][8][4];
    #pragma unroll
    for (int mt = 0; mt < 4; mt++)
        #pragma unroll
        for (int nt = 0; nt < 8; nt++)
            #pragma unroll
            for (int r = 0; r < 4; r++) acc[mt][nt][r] = 0.f;

    const int KT = K >> 4;

    // prologue: load tile 0 into buffer 0
    {
        float4 av0 = *(const float4*)(A + (size_t)(bm + (tid >> 2)) * K + ac4 * 4);
        float4 av1 = *(const float4*)(A + (size_t)(bm + ((tid + 256) >> 2)) * K + ac4 * 4);
        float4 bv[4];
        #pragma unroll
        for (int i = 0; i < 4; i++) {
            int slot = tid + i * 256;
            bv[i] = *(const float4*)(B + (size_t)(slot >> 6) * N + bn + (slot & 63) * 4);
        }
        // split + store A
        const float* a0 = (const float*)&av0;
        const float* a1 = (const float*)&av1;
        #pragma unroll
        for (int c = 0; c < 4; c++) {
            uint32_t h = f2tf(a0[c]);
            sAh[(tid >> 2) * ASTRIDE + ac4 * 4 + c] = h;
            sAl[(tid >> 2) * ASTRIDE + ac4 * 4 + c] = f2tf(a0[c] - __uint_as_float(h));
            uint32_t h1 = f2tf(a1[c]);
            sAh[((tid + 256) >> 2) * ASTRIDE + ac4 * 4 + c] = h1;
            sAl[((tid + 256) >> 2) * ASTRIDE + ac4 * 4 + c] = f2tf(a1[c] - __uint_as_float(h1));
        }
        #pragma unroll
        for (int i = 0; i < 4; i++) {
            int slot = tid + i * 256;
            const float* bp = (const float*)&bv[i];
            #pragma unroll
            for (int c = 0; c < 4; c++) {
                uint32_t h = f2tf(bp[c]);
                sBh[(slot >> 6) * BSTRIDE + (slot & 63) * 4 + c] = h;
                sBl[(slot >> 6) * BSTRIDE + (slot & 63) * 4 + c] = f2tf(bp[c] - __uint_as_float(h));
            }
        }
    }
    __syncthreads();

    for (int kt = 0; kt < KT; kt++) {
        const int p = kt & 1;
        const uint32_t* Ah = sAh + p * A_BUF;
        const uint32_t* Al = sAl + p * A_BUF;
        const uint32_t* Bh = sBh + p * B_BUF;
        const uint32_t* Bl = sBl + p * B_BUF;

        // prefetch next tile (gmem -> regs)
        float4 av0, av1, bv[4];
        const bool more = (kt + 1 < KT);
        if (more) {
            int k0 = (kt + 1) << 4;
            av0 = *(const float4*)(A + (size_t)(bm + (tid >> 2)) * K + k0 + ac4 * 4);
            av1 = *(const float4*)(A + (size_t)(bm + ((tid + 256) >> 2)) * K + k0 + ac4 * 4);
            #pragma unroll
            for (int i = 0; i < 4; i++) {
                int slot = tid + i * 256;
                bv[i] = *(const float4*)(B + (size_t)(k0 + (slot >> 6)) * N + bn + (slot & 63) * 4);
            }
        }

        // compute on buffer p: two k8 sub-steps
        #pragma unroll
        for (int kk = 0; kk < 16; kk += 8) {
            uint32_t ah[4][4], al[4][4];
            #pragma unroll
            for (int mt = 0; mt < 4; mt++) {
                int rb = wm * 64 + mt * 16 + g;
                ah[mt][0] = Ah[rb * ASTRIDE + kk + kq];
                ah[mt][1] = Ah[(rb + 8) * ASTRIDE + kk + kq];
                ah[mt][2] = Ah[rb * ASTRIDE + kk + kq + 4];
                ah[mt][3] = Ah[(rb + 8) * ASTRIDE + kk + kq + 4];
                al[mt][0] = Al[rb * ASTRIDE + kk + kq];
                al[mt][1] = Al[(rb + 8) * ASTRIDE + kk + kq];
                al[mt][2] = Al[rb * ASTRIDE + kk + kq + 4];
                al[mt][3] = Al[(rb + 8) * ASTRIDE + kk + kq + 4];
            }
            #pragma unroll
            for (int nt = 0; nt < 8; nt++) {
                int n = wn * 64 + nt * 8 + g;
                uint32_t bh0 = Bh[(kk + kq) * BSTRIDE + n];
                uint32_t bh1 = Bh[(kk + kq + 4) * BSTRIDE + n];
                uint32_t bl0 = Bl[(kk + kq) * BSTRIDE + n];
                uint32_t bl1 = Bl[(kk + kq + 4) * BSTRIDE + n];
                #pragma unroll
                for (int mt = 0; mt < 4; mt++) {
                    MMA_TF32(acc[mt][nt], al[mt], bh0, bh1);
                    MMA_TF32(acc[mt][nt], ah[mt], bl0, bl1);
                    MMA_TF32(acc[mt][nt], ah[mt], bh0, bh1);
                }
            }
        }

        // split + store next tile into buffer p^1
        if (more) {
            uint32_t* nAh = sAh + (p ^ 1) * A_BUF;
            uint32_t* nAl = sAl + (p ^ 1) * A_BUF;
            uint32_t* nBh = sBh + (p ^ 1) * B_BUF;
            uint32_t* nBl = sBl + (p ^ 1) * B_BUF;
            const float* a0 = (const float*)&av0;
            const float* a1 = (const float*)&av1;
            #pragma unroll
            for (int c = 0; c < 4; c++) {
                uint32_t h = f2tf(a0[c]);
                nAh[(tid >> 2) * ASTRIDE + ac4 * 4 + c] = h;
                nAl[(tid >> 2) * ASTRIDE + ac4 * 4 + c] = f2tf(a0[c] - __uint_as_float(h));
                uint32_t h1 = f2tf(a1[c]);
                nAh[((tid + 256) >> 2) * ASTRIDE + ac4 * 4 + c] = h1;
                nAl[((tid + 256) >> 2) * ASTRIDE + ac4 * 4 + c] = f2tf(a1[c] - __uint_as_float(h1));
            }
            #pragma unroll
            for (int i = 0; i < 4; i++) {
                int slot = tid + i * 256;
                const float* bp = (const float*)&bv[i];
                #pragma unroll
                for (int c = 0; c < 4; c++) {
                    uint32_t h = f2tf(bp[c]);
                    nBh[(slot >> 6) * BSTRIDE + (slot & 63) * 4 + c] = h;
                    nBl[(slot >> 6) * BSTRIDE + (slot & 63) * 4 + c] = f2tf(bp[c] - __uint_as_float(h));
                }
            }
        }
        __syncthreads();
    }

    // epilogue
    #pragma unroll
    for (int mt = 0; mt < 4; mt++) {
        int m0 = bm + wm * 64 + mt * 16 + g;
        #pragma unroll
        for (int nt = 0; nt < 8; nt++) {
            int n0 = bn + wn * 64 + nt * 8 + kq * 2;
            #pragma unroll
            for (int r = 0; r < 4; r++) {
                int m = m0 + (r >> 1) * 8;
                int n = n0 + (r & 1);
                float c = acc[mt][nt][r] + bias[n];
                size_t idx = (size_t)m * N + n;
                if (EPI == 0) {
                    C[idx] = 0.5f * c * (1.0f + erff(c * 0.70710678118654752f));
                } else {
                    C[idx] += c;
                }
            }
        }
    }
}

__global__ void __launch_bounds__(256, 1) gemm1_tf32(const float* __restrict__ W1,
                                                     const float* __restrict__ b1) {
    gemm_tf32_core<0>(g_s2, W1, b1, g_act, NTOK, HH, DD);
}
__global__ void __launch_bounds__(256, 1) gemm2_tf32(const float* __restrict__ W2,
                                                     const float* __restrict__ b2) {
    gemm_tf32_core<1>(g_act, W2, b2, g_h, NTOK, DD, HH);
}

// ---------------- fp32 SGEMM (kept for the small output projection) --------
__global__ void __launch_bounds__(256) gemm_out_kernel(const float* __restrict__ embed,
                                                       float* __restrict__ out) {
    __shared__ float As[16][128];
    __shared__ float Bs[16][132];
    const float* A = g_h;
    const float* B = embed;   // [VV][DD] row-major, used as B^T
    const int N = VV, K = DD;
    const int bm = blockIdx.y * 128, bn = blockIdx.x * 128;
    const int tid = threadIdx.x;
    const int ty = tid >> 4, tx = tid & 15;
    float acc[8][8];
    #pragma unroll
    for (int i = 0; i < 8; i++)
        #pragma unroll
        for (int j = 0; j < 8; j++) acc[i][j] = 0.f;

    for (int k0 = 0; k0 < K; k0 += 16) {
        #pragma unroll
        for (int r = 0; r < 2; r++) {
            int slot = tid + r * 256;
            int arow = slot >> 2;
            int ac = (slot & 3) << 2;
            const float4 v = *(const float4*)(A + (size_t)(bm + arow) * K + k0 + ac);
            As[ac + 0][arow] = v.x;
            As[ac + 1][arow] = v.y;
            As[ac + 2][arow] = v.z;
            As[ac + 3][arow] = v.w;
        }
        #pragma unroll
        for (int r = 0; r < 2; r++) {
            int slot = tid + r * 256;
            int nr = slot >> 2;
            int kc = (slot & 3) << 2;
            const float4 v = *(const float4*)(B + (size_t)(bn + nr) * K + k0 + kc);
            Bs[kc + 0][nr] = v.x;
            Bs[kc + 1][nr] = v.y;
            Bs[kc + 2][nr] = v.z;
            Bs[kc + 3][nr] = v.w;
        }
        __syncthreads();
        #pragma unroll
        for (int kk = 0; kk < 16; kk++) {
            float ra[8], rb[8];
            *(float4*)&ra[0] = *(const float4*)&As[kk][ty * 8];
            *(float4*)&ra[4] = *(const float4*)&As[kk][ty * 8 + 4];
            *(float4*)&rb[0] = *(const float4*)&Bs[kk][tx * 8];
            *(float4*)&rb[4] = *(const float4*)&Bs[kk][tx * 8 + 4];
            #pragma unroll
            for (int i = 0; i < 8; i++)
                #pragma unroll
                for (int j = 0; j < 8; j++) acc[i][j] += ra[i] * rb[j];
        }
        __syncthreads();
    }

    int row0 = bm + ty * 8, col0 = bn + tx * 8;
    #pragma unroll
    for (int i = 0; i < 8; i++)
        #pragma unroll
        for (int j = 0; j < 8; j++)
            out[(size_t)(row0 + i) * N + col0 + j] = acc[i][j];
}

// ---------------- launcher ----------------
extern "C" void kernel_launch(void* const* d_in, const int* in_sizes, int n_in,
                              void* d_out, int out_size) {
    const int*   x     = (const int*)d_in[0];
    const float* embed = (const float*)d_in[1];
    const float* kpar  = (const float*)d_in[2];
    const float* gamma = (const float*)d_in[3];
    const float* beta  = (const float*)d_in[4];
    const float* W1    = (const float*)d_in[5];
    const float* b1    = (const float*)d_in[6];
    const float* W2    = (const float*)d_in[7];
    const float* b2    = (const float*)d_in[8];
    float* out = (float*)d_out;

    cudaFuncSetAttribute(gemm1_tf32, cudaFuncAttributeMaxDynamicSharedMemorySize, GSMEM_BYTES);
    cudaFuncSetAttribute(gemm2_tf32, cudaFuncAttributeMaxDynamicSharedMemorySize, GSMEM_BYTES);

    dim3 sg(BB, NCH);

    embed_kernel<<<(NTOK * DD) / 256, 256>>>(x, embed);
    cumprod_tanh_kernel<<<NTOK, DD>>>();
    boundA_kernel<<<sg, DD>>>();
    boundB_kernel<<<BB, DD>>>();
    boundC_kernel<<<sg, DD>>>();

    for (int l = 0; l < 3; l++) {
        scanA_kernel<<<sg, DD>>>(kpar, l);
        scanB_kernel<<<BB, DD>>>(kpar, l);
        magC_kernel<<<sg, DD>>>();
        decayC_kernel<<<sg, DD>>>(kpar, l);
        layernorm_kernel<<<NTOK, 128>>>(gamma + l * DD, beta + l * DD);
        gemm1_tf32<<<dim3(HH / 256, NTOK / 128), 256, GSMEM_BYTES>>>(W1 + (size_t)l * DD * HH, b1 + l * HH);
        gemm2_tf32<<<dim3(DD / 256, NTOK / 128), 256, GSMEM_BYTES>>>(W2 + (size_t)l * HH * DD, b2 + l * DD);
    }
    gemm_out_kernel<<<dim3(VV / 128, NTOK / 128), 256>>>(embed, out);
}

// round 4
// speedup vs baseline: 2.4773x; 1.6492x over previous
#include <cuda_runtime.h>
#include <cuda_bf16.h>
#include <math.h>
#include <stdint.h>

#define BB 4
#define TT 2048
#define DD 512
#define HH 2048
#define VV 256
#define NTOK (BB*TT)   // 8192
#define CS 64
#define NCH (TT/CS)

// ---------------- scratch ----------------
__device__ __align__(128) float g_h[NTOK*DD];
__device__ __align__(128) float g_s1[NTOK*DD];
__device__ __align__(128) float g_partA[BB*NCH*DD];
__device__ __align__(128) float g_partB[BB*NCH*DD];
__device__ __align__(128) __nv_bfloat16 g_s2h[NTOK*DD];
__device__ __align__(128) __nv_bfloat16 g_s2l[NTOK*DD];
__device__ __align__(128) __nv_bfloat16 g_acth[(size_t)NTOK*HH];
__device__ __align__(128) __nv_bfloat16 g_actl[(size_t)NTOK*HH];
__device__ __align__(128) __nv_bfloat16 g_w1h[3*DD*HH];
__device__ __align__(128) __nv_bfloat16 g_w1l[3*DD*HH];
__device__ __align__(128) __nv_bfloat16 g_w2h[3*DD*HH];
__device__ __align__(128) __nv_bfloat16 g_w2l[3*DD*HH];

__device__ __forceinline__ float softplus_lambda(float kv) {
    float sp = (kv > 0.f) ? (kv + log1pf(expf(-kv))) : log1pf(expf(kv));
    return expf(-sp);
}

// ---------------- embedding gather ----------------
__global__ void embed_kernel(const int* __restrict__ x, const float* __restrict__ embed) {
    int i = blockIdx.x * blockDim.x + threadIdx.x;
    int tok = i >> 9;
    int d = i & (DD - 1);
    g_h[i] = embed[x[tok] * DD + d];
}

// ---------------- weight split prepass (bf16 hi/lo) ----------------
__global__ void split_weights_kernel(const float* __restrict__ W1, const float* __restrict__ W2) {
    size_t i = (size_t)blockIdx.x * blockDim.x + threadIdx.x;  // over 3*DD*HH
    float v1 = W1[i];
    __nv_bfloat16 h1 = __float2bfloat16(v1);
    g_w1h[i] = h1;
    g_w1l[i] = __float2bfloat16(v1 - __bfloat162float(h1));
    float v2 = W2[i];
    __nv_bfloat16 h2 = __float2bfloat16(v2);
    g_w2h[i] = h2;
    g_w2l[i] = __float2bfloat16(v2 - __bfloat162float(h2));
}

// ---------------- tanh(cumprod over feature dim) -> s1 ----------------
__global__ void cumprod_tanh_kernel() {
    __shared__ float s[DD];
    int tok = blockIdx.x;
    int d = threadIdx.x;
    size_t base = (size_t)tok * DD;
    s[d] = g_h[base + d];
    __syncthreads();
    #pragma unroll
    for (int off = 1; off < DD; off <<= 1) {
        float t = (d >= off) ? s[d - off] : 1.0f;
        __syncthreads();
        s[d] *= t;
        __syncthreads();
    }
    g_s1[base + d] = tanhf(s[d]);
}

// ============= boundary scan ================================================
__global__ void boundA_kernel() {
    int b = blockIdx.x, ch = blockIdx.y, d = threadIdx.x;
    size_t base = ((size_t)b * TT + ch * CS) * DD + d;
    float s = 0.f;
    #pragma unroll 8
    for (int i = 0; i < CS; i++) s += g_s1[base + (size_t)i * DD];
    g_partA[((size_t)b * NCH + ch) * DD + d] = s;
}

__global__ void boundB_kernel() {
    int b = blockIdx.x, d = threadIdx.x;
    float c = 0.f;
    for (int ch = 0; ch < NCH; ch++) {
        size_t idx = ((size_t)b * NCH + ch) * DD + d;
        float v = g_partA[idx];
        g_partA[idx] = c;
        c += v;
    }
}

__global__ void boundC_kernel() {
    int b = blockIdx.x, ch = blockIdx.y, d = threadIdx.x;
    size_t base = ((size_t)b * TT + ch * CS) * DD + d;
    float acc = g_partA[((size_t)b * NCH + ch) * DD + d];
    #pragma unroll 4
    for (int i = 0; i < CS; i++) {
        size_t idx = base + (size_t)i * DD;
        acc += g_s1[idx];
        g_h[idx] = g_h[idx] * (1.0f + acc);
    }
}

// ============= per-layer scans =============================================
__global__ void scanA_kernel(const float* __restrict__ kpar, int l) {
    int b = blockIdx.x, ch = blockIdx.y, d = threadIdx.x;
    float lam = softplus_lambda(kpar[l]);
    size_t base = ((size_t)b * TT + ch * CS) * DD + d;
    float s = 0.f, loc = 0.f;
    #pragma unroll 4
    for (int i = 0; i < CS; i++) {
        float v = g_h[base + (size_t)i * DD];
        s += v;
        loc = v + lam * loc;
    }
    size_t pidx = ((size_t)b * NCH + ch) * DD + d;
    g_partA[pidx] = s;
    g_partB[pidx] = loc;
}

__global__ void scanB_kernel(const float* __restrict__ kpar, int l) {
    int b = blockIdx.x, d = threadIdx.x;
    float lam = softplus_lambda(kpar[l]);
    float lamCS = powf(lam, (float)CS);
    float c1 = 0.f, c2 = 0.f;
    for (int ch = 0; ch < NCH; ch++) {
        size_t idx = ((size_t)b * NCH + ch) * DD + d;
        float a = g_partA[idx];
        float v = g_partB[idx];
        g_partA[idx] = c1;
        g_partB[idx] = c2;
        c1 += a;
        c2 = v + lamCS * c2;
    }
}

// ======== fused mag + decay-ctx: ctx=|mag*S| -> s1 (g_mag stays in smem) ===
__global__ void magdecayC_kernel(const float* __restrict__ kpar, int l) {
    __shared__ float accw[CS][17];
    __shared__ float smag[CS];
    int b = blockIdx.x, ch = blockIdx.y;
    int d = threadIdx.x;
    int lane = d & 31, wid = d >> 5;
    int t0 = ch * CS;
    size_t base = ((size_t)b * TT + t0) * DD + d;
    float acc = g_partA[((size_t)b * NCH + ch) * DD + d];
    float hp = (t0 > 0) ? g_h[base - DD] : 0.f;
    #pragma unroll 4
    for (int i = 0; i < CS; i++) {
        float v = g_h[base + (size_t)i * DD];
        acc += v;
        float diff = acc - hp;
        float sq = diff * diff;
        #pragma unroll
        for (int o = 16; o; o >>= 1) sq += __shfl_down_sync(0xffffffffu, sq, o);
        if (lane == 0) accw[i][wid] = sq;
        hp = v;
    }
    __syncthreads();
    if (d < CS) {
        float s = 0.f;
        #pragma unroll
        for (int w = 0; w < 16; w++) s += accw[d][w];
        smag[d] = sqrtf(s);
    }
    __syncthreads();
    float lam = softplus_lambda(kpar[l]);
    float S = g_partB[((size_t)b * NCH + ch) * DD + d];
    #pragma unroll 4
    for (int i = 0; i < CS; i++) {
        size_t idx = base + (size_t)i * DD;
        S = g_h[idx] + lam * S;
        g_s1[idx] = fabsf(smag[i] * S);
    }
}

// ---------------- block reduction ----------------
__device__ __forceinline__ float block_reduce(float v, float* sh) {
    int lane = threadIdx.x & 31, wid = threadIdx.x >> 5;
    #pragma unroll
    for (int o = 16; o; o >>= 1) v += __shfl_down_sync(0xffffffffu, v, o);
    if (lane == 0) sh[wid] = v;
    __syncthreads();
    float r = 0.f;
    if (threadIdx.x < (blockDim.x >> 5)) r = sh[threadIdx.x];
    if (wid == 0) {
        #pragma unroll
        for (int o = 16; o; o >>= 1) r += __shfl_down_sync(0xffffffffu, r, o);
        if (lane == 0) sh[0] = r;
    }
    __syncthreads();
    r = sh[0];
    __syncthreads();
    return r;
}

// ---------------- layernorm -> pre-split bf16 s2 ----------------
__global__ void layernorm_kernel(const float* __restrict__ gamma, const float* __restrict__ beta) {
    __shared__ float row[DD];
    __shared__ float sh[32];
    int tok = blockIdx.x;
    size_t base = (size_t)tok * DD;
    float s = 0.f;
    for (int d = threadIdx.x; d < DD; d += blockDim.x) {
        float v = g_s1[base + d];
        row[d] = v;
        s += v;
    }
    s = block_reduce(s, sh);
    float mu = s * (1.0f / DD);
    float q = 0.f;
    for (int d = threadIdx.x; d < DD; d += blockDim.x) {
        float v = row[d] - mu;
        q += v * v;
    }
    q = block_reduce(q, sh);
    float rstd = rsqrtf(q * (1.0f / DD) + 1e-3f);
    for (int d = threadIdx.x; d < DD; d += blockDim.x) {
        float y = (row[d] - mu) * rstd * gamma[d] + beta[d];
        __nv_bfloat16 h = __float2bfloat16(y);
        g_s2h[base + d] = h;
        g_s2l[base + d] = __float2bfloat16(y - __bfloat162float(h));
    }
}

// ================= bf16x3 tensor-core GEMM (ldmatrix + m16n8k16) ===========
// Block 128x256x16, 8 warps (2m x 4n), warp tile 64x64, double-buffered smem.
#define AROWB 48                       // bytes per A smem row (32B data + pad)
#define A_TILE_B (128*AROWB)           // 6144
#define BROWB 528                      // bytes per B smem k-row (512B + pad)
#define B_TILE_B (16*BROWB)            // 8448
#define SM_A_BYTES (4*A_TILE_B)        // 2 buf x (hi+lo)
#define SM_B_BYTES (4*B_TILE_B)
#define GSMEM (SM_A_BYTES + SM_B_BYTES)  // 58368

#define LDSM4(r0,r1,r2,r3,addr) \
    asm volatile("ldmatrix.sync.aligned.m8n8.x4.shared.b16 {%0,%1,%2,%3},[%4];" \
                 : "=r"(r0),"=r"(r1),"=r"(r2),"=r"(r3) : "r"(addr))
#define LDSM4T(r0,r1,r2,r3,addr) \
    asm volatile("ldmatrix.sync.aligned.m8n8.x4.trans.shared.b16 {%0,%1,%2,%3},[%4];" \
                 : "=r"(r0),"=r"(r1),"=r"(r2),"=r"(r3) : "r"(addr))
#define MMA_BF16(c,a,b0,b1) \
    asm volatile("mma.sync.aligned.m16n8k16.row.col.f32.bf16.bf16.f32 " \
                 "{%0,%1,%2,%3},{%4,%5,%6,%7},{%8,%9},{%0,%1,%2,%3};" \
                 : "+f"(c[0]),"+f"(c[1]),"+f"(c[2]),"+f"(c[3]) \
                 : "r"(a[0]),"r"(a[1]),"r"(a[2]),"r"(a[3]),"r"(b0),"r"(b1))

struct StageRegs { uint4 ah, al, bh0, bh1, bl0, bl1; };

__device__ __forceinline__ void ldg_tile(const __nv_bfloat16* __restrict__ Ah,
                                         const __nv_bfloat16* __restrict__ Al,
                                         const __nv_bfloat16* __restrict__ Bh,
                                         const __nv_bfloat16* __restrict__ Bl,
                                         int bm, int bn, int k0, int K, int N,
                                         int tid, StageRegs& r) {
    int arow = tid >> 1, aseg = tid & 1;
    size_t abase = (size_t)(bm + arow) * K + k0 + aseg * 8;
    r.ah = *(const uint4*)(Ah + abase);
    r.al = *(const uint4*)(Al + abase);
    int k = tid >> 5, ng = tid & 31;
    size_t bbase0 = (size_t)(k0 + k) * N + bn + ng * 8;
    size_t bbase1 = (size_t)(k0 + k + 8) * N + bn + ng * 8;
    r.bh0 = *(const uint4*)(Bh + bbase0);
    r.bh1 = *(const uint4*)(Bh + bbase1);
    r.bl0 = *(const uint4*)(Bl + bbase0);
    r.bl1 = *(const uint4*)(Bl + bbase1);
}

__device__ __forceinline__ void sts_tile(char* sbase, int p, int tid, const StageRegs& r) {
    int arow = tid >> 1, aseg = tid & 1;
    char* A = sbase + p * (2 * A_TILE_B);
    *(uint4*)(A + arow * AROWB + aseg * 16) = r.ah;
    *(uint4*)(A + A_TILE_B + arow * AROWB + aseg * 16) = r.al;
    int k = tid >> 5, ng = tid & 31;
    char* Bp = sbase + SM_A_BYTES + p * (2 * B_TILE_B);
    *(uint4*)(Bp + k * BROWB + ng * 16) = r.bh0;
    *(uint4*)(Bp + (k + 8) * BROWB + ng * 16) = r.bh1;
    *(uint4*)(Bp + B_TILE_B + k * BROWB + ng * 16) = r.bl0;
    *(uint4*)(Bp + B_TILE_B + (k + 8) * BROWB + ng * 16) = r.bl1;
}

__device__ __forceinline__ float gelu_exact(float c) {
    return 0.5f * c * (1.0f + erff(c * 0.70710678118654752f));
}

// EPI: 0 = bias+GELU -> pre-split packed bf16 hi/lo outputs; 1 = bias+accum into Cf
template <int EPI>
__device__ __forceinline__ void gemm_bf16x3(const __nv_bfloat16* __restrict__ Ah,
                                            const __nv_bfloat16* __restrict__ Al,
                                            const __nv_bfloat16* __restrict__ Bh,
                                            const __nv_bfloat16* __restrict__ Bl,
                                            const float* __restrict__ bias,
                                            float* __restrict__ Cf,
                                            __nv_bfloat16* __restrict__ Ch,
                                            __nv_bfloat16* __restrict__ Cl,
                                            int M, int N, int K) {
    extern __shared__ char smc[];
    const int bm = blockIdx.y * 128;
    const int bn = blockIdx.x * 256;
    const int tid = threadIdx.x;
    const int lane = tid & 31;
    const int wid = tid >> 5;
    const int wm = wid >> 2, wn = wid & 3;
    const int g = lane >> 2, kq = lane & 3;
    const int lrow = lane & 7, lmat = lane >> 3;

    const uint32_t smem_u32 = (uint32_t)__cvta_generic_to_shared(smc);
    const uint32_t aoff = smem_u32 + (uint32_t)((wm * 64 + (lmat & 1) * 8 + lrow) * AROWB + (lmat >> 1) * 16);
    const uint32_t boff = smem_u32 + SM_A_BYTES +
                          (uint32_t)(((lmat & 1) * 8 + lrow) * BROWB + (wn * 64 + (lmat >> 1) * 8) * 2);

    float acc[4][8][4];
    #pragma unroll
    for (int mt = 0; mt < 4; mt++)
        #pragma unroll
        for (int nt = 0; nt < 8; nt++)
            #pragma unroll
            for (int r = 0; r < 4; r++) acc[mt][nt][r] = 0.f;

    const int KT = K >> 4;
    StageRegs sr;
    ldg_tile(Ah, Al, Bh, Bl, bm, bn, 0, K, N, tid, sr);
    sts_tile(smc, 0, tid, sr);
    __syncthreads();

    for (int kt = 0; kt < KT; kt++) {
        const int p = kt & 1;
        const bool more = (kt + 1 < KT);
        if (more) ldg_tile(Ah, Al, Bh, Bl, bm, bn, (kt + 1) << 4, K, N, tid, sr);

        const uint32_t aB = aoff + p * (2 * A_TILE_B);
        const uint32_t bB = boff + p * (2 * B_TILE_B);
        uint32_t aH[4][4], aL[4][4];
        #pragma unroll
        for (int mt = 0; mt < 4; mt++) {
            LDSM4(aH[mt][0], aH[mt][1], aH[mt][2], aH[mt][3], aB + mt * (16 * AROWB));
            LDSM4(aL[mt][0], aL[mt][1], aL[mt][2], aL[mt][3], aB + mt * (16 * AROWB) + A_TILE_B);
        }
        #pragma unroll
        for (int ntp = 0; ntp < 4; ntp++) {
            uint32_t bh[4], bl[4];
            LDSM4T(bh[0], bh[1], bh[2], bh[3], bB + ntp * 32);
            LDSM4T(bl[0], bl[1], bl[2], bl[3], bB + ntp * 32 + B_TILE_B);
            #pragma unroll
            for (int w = 0; w < 2; w++) {
                const int nt = 2 * ntp + w;
                #pragma unroll
                for (int mt = 0; mt < 4; mt++) {
                    MMA_BF16(acc[mt][nt], aL[mt], bh[2 * w], bh[2 * w + 1]);
                    MMA_BF16(acc[mt][nt], aH[mt], bl[2 * w], bl[2 * w + 1]);
                    MMA_BF16(acc[mt][nt], aH[mt], bh[2 * w], bh[2 * w + 1]);
                }
            }
        }
        if (more) sts_tile(smc, p ^ 1, tid, sr);
        __syncthreads();
    }

    // epilogue
    #pragma unroll
    for (int mt = 0; mt < 4; mt++) {
        const int m0 = bm + wm * 64 + mt * 16 + g;
        #pragma unroll
        for (int nt = 0; nt < 8; nt++) {
            const int n0 = bn + wn * 64 + nt * 8 + kq * 2;
            const float b0 = bias[n0], b1 = bias[n0 + 1];
            if (EPI == 0) {
                float v0 = gelu_exact(acc[mt][nt][0] + b0);
                float v1 = gelu_exact(acc[mt][nt][1] + b1);
                float v2 = gelu_exact(acc[mt][nt][2] + b0);
                float v3 = gelu_exact(acc[mt][nt][3] + b1);
                __nv_bfloat16 h0 = __float2bfloat16(v0), h1 = __float2bfloat16(v1);
                __nv_bfloat16 h2 = __float2bfloat16(v2), h3 = __float2bfloat16(v3);
                uint32_t hw0 = (uint32_t)__bfloat16_as_ushort(h0) | ((uint32_t)__bfloat16_as_ushort(h1) << 16);
                uint32_t hw1 = (uint32_t)__bfloat16_as_ushort(h2) | ((uint32_t)__bfloat16_as_ushort(h3) << 16);
                __nv_bfloat16 l0 = __float2bfloat16(v0 - __bfloat162float(h0));
                __nv_bfloat16 l1 = __float2bfloat16(v1 - __bfloat162float(h1));
                __nv_bfloat16 l2 = __float2bfloat16(v2 - __bfloat162float(h2));
                __nv_bfloat16 l3 = __float2bfloat16(v3 - __bfloat162float(h3));
                uint32_t lw0 = (uint32_t)__bfloat16_as_ushort(l0) | ((uint32_t)__bfloat16_as_ushort(l1) << 16);
                uint32_t lw1 = (uint32_t)__bfloat16_as_ushort(l2) | ((uint32_t)__bfloat16_as_ushort(l3) << 16);
                size_t i0 = ((size_t)m0 * N + n0) >> 1;
                size_t i1 = ((size_t)(m0 + 8) * N + n0) >> 1;
                ((uint32_t*)Ch)[i0] = hw0;
                ((uint32_t*)Cl)[i0] = lw0;
                ((uint32_t*)Ch)[i1] = hw1;
                ((uint32_t*)Cl)[i1] = lw1;
            } else {
                float2* p0 = (float2*)&Cf[(size_t)m0 * N + n0];
                float2* p1 = (float2*)&Cf[(size_t)(m0 + 8) * N + n0];
                float2 o0 = *p0, o1 = *p1;
                o0.x += acc[mt][nt][0] + b0;
                o0.y += acc[mt][nt][1] + b1;
                o1.x += acc[mt][nt][2] + b0;
                o1.y += acc[mt][nt][3] + b1;
                *p0 = o0;
                *p1 = o1;
            }
        }
    }
}

__global__ void __launch_bounds__(256, 1) gemm1_bf16(const float* __restrict__ b1, int l) {
    gemm_bf16x3<0>(g_s2h, g_s2l, g_w1h + (size_t)l * DD * HH, g_w1l + (size_t)l * DD * HH,
                   b1, nullptr, g_acth, g_actl, NTOK, HH, DD);
}
__global__ void __launch_bounds__(256, 1) gemm2_bf16(const float* __restrict__ b2, int l) {
    gemm_bf16x3<1>(g_acth, g_actl, g_w2h + (size_t)l * DD * HH, g_w2l + (size_t)l * DD * HH,
                   b2, g_h, nullptr, nullptr, NTOK, DD, HH);
}

// ---------------- fp32 SGEMM for output projection --------------------------
__global__ void __launch_bounds__(256) gemm_out_kernel(const float* __restrict__ embed,
                                                       float* __restrict__ out) {
    __shared__ float As[16][128];
    __shared__ float Bs[16][132];
    const float* A = g_h;
    const float* B = embed;
    const int N = VV, K = DD;
    const int bm = blockIdx.y * 128, bn = blockIdx.x * 128;
    const int tid = threadIdx.x;
    const int ty = tid >> 4, tx = tid & 15;
    float acc[8][8];
    #pragma unroll
    for (int i = 0; i < 8; i++)
        #pragma unroll
        for (int j = 0; j < 8; j++) acc[i][j] = 0.f;

    for (int k0 = 0; k0 < K; k0 += 16) {
        #pragma unroll
        for (int r = 0; r < 2; r++) {
            int slot = tid + r * 256;
            int arow = slot >> 2;
            int ac = (slot & 3) << 2;
            const float4 v = *(const float4*)(A + (size_t)(bm + arow) * K + k0 + ac);
            As[ac + 0][arow] = v.x;
            As[ac + 1][arow] = v.y;
            As[ac + 2][arow] = v.z;
            As[ac + 3][arow] = v.w;
        }
        #pragma unroll
        for (int r = 0; r < 2; r++) {
            int slot = tid + r * 256;
            int nr = slot >> 2;
            int kc = (slot & 3) << 2;
            const float4 v = *(const float4*)(B + (size_t)(bn + nr) * K + k0 + kc);
            Bs[kc + 0][nr] = v.x;
            Bs[kc + 1][nr] = v.y;
            Bs[kc + 2][nr] = v.z;
            Bs[kc + 3][nr] = v.w;
        }
        __syncthreads();
        #pragma unroll
        for (int kk = 0; kk < 16; kk++) {
            float ra[8], rb[8];
            *(float4*)&ra[0] = *(const float4*)&As[kk][ty * 8];
            *(float4*)&ra[4] = *(const float4*)&As[kk][ty * 8 + 4];
            *(float4*)&rb[0] = *(const float4*)&Bs[kk][tx * 8];
            *(float4*)&rb[4] = *(const float4*)&Bs[kk][tx * 8 + 4];
            #pragma unroll
            for (int i = 0; i < 8; i++)
                #pragma unroll
                for (int j = 0; j < 8; j++) acc[i][j] += ra[i] * rb[j];
        }
        __syncthreads();
    }

    int row0 = bm + ty * 8, col0 = bn + tx * 8;
    #pragma unroll
    for (int i = 0; i < 8; i++)
        #pragma unroll
        for (int j = 0; j < 8; j++)
            out[(size_t)(row0 + i) * N + col0 + j] = acc[i][j];
}

// ---------------- launcher ----------------
extern "C" void kernel_launch(void* const* d_in, const int* in_sizes, int n_in,
                              void* d_out, int out_size) {
    const int*   x     = (const int*)d_in[0];
    const float* embed = (const float*)d_in[1];
    const float* kpar  = (const float*)d_in[2];
    const float* gamma = (const float*)d_in[3];
    const float* beta  = (const float*)d_in[4];
    const float* W1    = (const float*)d_in[5];
    const float* b1    = (const float*)d_in[6];
    const float* W2    = (const float*)d_in[7];
    const float* b2    = (const float*)d_in[8];
    float* out = (float*)d_out;

    cudaFuncSetAttribute(gemm1_bf16, cudaFuncAttributeMaxDynamicSharedMemorySize, GSMEM);
    cudaFuncSetAttribute(gemm2_bf16, cudaFuncAttributeMaxDynamicSharedMemorySize, GSMEM);

    dim3 sg(BB, NCH);

    embed_kernel<<<(NTOK * DD) / 256, 256>>>(x, embed);
    split_weights_kernel<<<(3 * DD * HH) / 256, 256>>>(W1, W2);
    cumprod_tanh_kernel<<<NTOK, DD>>>();
    boundA_kernel<<<sg, DD>>>();
    boundB_kernel<<<BB, DD>>>();
    boundC_kernel<<<sg, DD>>>();

    for (int l = 0; l < 3; l++) {
        scanA_kernel<<<sg, DD>>>(kpar, l);
        scanB_kernel<<<BB, DD>>>(kpar, l);
        magdecayC_kernel<<<sg, DD>>>(kpar, l);
        layernorm_kernel<<<NTOK, 128>>>(gamma + l * DD, beta + l * DD);
        gemm1_bf16<<<dim3(HH / 256, NTOK / 128), 256, GSMEM>>>(b1 + l * HH, l);
        gemm2_bf16<<<dim3(DD / 256, NTOK / 128), 256, GSMEM>>>(b2 + l * DD, l);
    }
    gemm_out_kernel<<<dim3(VV / 128, NTOK / 128), 256>>>(embed, out);
}

// round 7
// speedup vs baseline: 2.4994x; 1.0089x over previous
#include <cuda_runtime.h>
#include <cuda_bf16.h>
#include <math.h>
#include <stdint.h>

#define BB 4
#define TT 2048
#define DD 512
#define HH 2048
#define VV 256
#define NTOK (BB*TT)   // 8192
#define CS 64
#define NCH (TT/CS)

// ---------------- scratch ----------------
__device__ __align__(128) float g_h[NTOK*DD];
__device__ __align__(128) float g_s1[NTOK*DD];
__device__ __align__(128) float g_partA[BB*NCH*DD];
__device__ __align__(128) float g_partB[BB*NCH*DD];
__device__ __align__(128) __nv_bfloat16 g_s2h[NTOK*DD];
__device__ __align__(128) __nv_bfloat16 g_s2l[NTOK*DD];
__device__ __align__(128) __nv_bfloat16 g_acth[(size_t)NTOK*HH];
__device__ __align__(128) __nv_bfloat16 g_actl[(size_t)NTOK*HH];
__device__ __align__(128) __nv_bfloat16 g_w1h[3*DD*HH];
__device__ __align__(128) __nv_bfloat16 g_w1l[3*DD*HH];
__device__ __align__(128) __nv_bfloat16 g_w2h[3*DD*HH];
__device__ __align__(128) __nv_bfloat16 g_w2l[3*DD*HH];

__device__ __forceinline__ float softplus_lambda(float kv) {
    float sp = (kv > 0.f) ? (kv + log1pf(expf(-kv))) : log1pf(expf(kv));
    return expf(-sp);
}

// ---------------- weight split prepass (bf16 hi/lo) ----------------
__global__ void split_weights_kernel(const float* __restrict__ W1, const float* __restrict__ W2) {
    size_t i = (size_t)blockIdx.x * blockDim.x + threadIdx.x;
    float v1 = W1[i];
    __nv_bfloat16 h1 = __float2bfloat16(v1);
    g_w1h[i] = h1;
    g_w1l[i] = __float2bfloat16(v1 - __bfloat162float(h1));
    float v2 = W2[i];
    __nv_bfloat16 h2 = __float2bfloat16(v2);
    g_w2h[i] = h2;
    g_w2l[i] = __float2bfloat16(v2 - __bfloat162float(h2));
}

// ---------------- fused embed gather + tanh(cumprod) (warp per token) ------
__global__ void embed_cumprod_kernel(const int* __restrict__ x, const float* __restrict__ embed) {
    int w = threadIdx.x >> 5;
    int lane = threadIdx.x & 31;
    int tok = blockIdx.x * 8 + w;
    const float* src = embed + (size_t)x[tok] * DD;
    size_t base = (size_t)tok * DD + lane * 16;
    float v[16];
    #pragma unroll
    for (int j = 0; j < 4; j++)
        *(float4*)&v[j * 4] = *(const float4*)(src + lane * 16 + j * 4);
    // local sequential inclusive cumprod
    float c[16];
    float run = 1.f;
    #pragma unroll
    for (int j = 0; j < 16; j++) {
        run *= v[j];
        c[j] = run;
    }
    // inclusive multiplicative warp scan of lane totals -> exclusive prefix
    float incl = run;
    #pragma unroll
    for (int off = 1; off < 32; off <<= 1) {
        float p = __shfl_up_sync(0xffffffffu, incl, off);
        if (lane >= off) incl *= p;
    }
    float pre = __shfl_up_sync(0xffffffffu, incl, 1);
    if (lane == 0) pre = 1.f;
    #pragma unroll
    for (int j = 0; j < 4; j++) {
        *(float4*)&g_h[base + j * 4] = *(const float4*)&v[j * 4];
        float4 o;
        o.x = tanhf(pre * c[j * 4 + 0]);
        o.y = tanhf(pre * c[j * 4 + 1]);
        o.z = tanhf(pre * c[j * 4 + 2]);
        o.w = tanhf(pre * c[j * 4 + 3]);
        *(float4*)&g_s1[base + j * 4] = o;
    }
}

// ============= boundary scan ================================================
__global__ void boundA_kernel() {
    int b = blockIdx.x, ch = blockIdx.y, d = threadIdx.x;
    size_t base = ((size_t)b * TT + ch * CS) * DD + d;
    float s = 0.f;
    #pragma unroll 8
    for (int i = 0; i < CS; i++) s += g_s1[base + (size_t)i * DD];
    g_partA[((size_t)b * NCH + ch) * DD + d] = s;
}

__global__ void boundB_kernel() {
    int b = blockIdx.x, d = threadIdx.x;
    float c = 0.f;
    for (int ch = 0; ch < NCH; ch++) {
        size_t idx = ((size_t)b * NCH + ch) * DD + d;
        float v = g_partA[idx];
        g_partA[idx] = c;
        c += v;
    }
}

__global__ void boundC_kernel() {
    int b = blockIdx.x, ch = blockIdx.y, d = threadIdx.x;
    size_t base = ((size_t)b * TT + ch * CS) * DD + d;
    float acc = g_partA[((size_t)b * NCH + ch) * DD + d];
    #pragma unroll 4
    for (int i = 0; i < CS; i++) {
        size_t idx = base + (size_t)i * DD;
        acc += g_s1[idx];
        g_h[idx] = g_h[idx] * (1.0f + acc);
    }
}

// ============= per-layer scans =============================================
__global__ void scanA_kernel(const float* __restrict__ kpar, int l) {
    int b = blockIdx.x, ch = blockIdx.y, d = threadIdx.x;
    float lam = softplus_lambda(kpar[l]);
    size_t base = ((size_t)b * TT + ch * CS) * DD + d;
    float s = 0.f, loc = 0.f;
    #pragma unroll 4
    for (int i = 0; i < CS; i++) {
        float v = g_h[base + (size_t)i * DD];
        s += v;
        loc = v + lam * loc;
    }
    size_t pidx = ((size_t)b * NCH + ch) * DD + d;
    g_partA[pidx] = s;
    g_partB[pidx] = loc;
}

__global__ void scanB_kernel(const float* __restrict__ kpar, int l) {
    int b = blockIdx.x, d = threadIdx.x;
    float lam = softplus_lambda(kpar[l]);
    float lamCS = powf(lam, (float)CS);
    float c1 = 0.f, c2 = 0.f;
    for (int ch = 0; ch < NCH; ch++) {
        size_t idx = ((size_t)b * NCH + ch) * DD + d;
        float a = g_partA[idx];
        float v = g_partB[idx];
        g_partA[idx] = c1;
        g_partB[idx] = c2;
        c1 += a;
        c2 = v + lamCS * c2;
    }
}

// ======== fused mag + decay-ctx ============================================
__global__ void magdecayC_kernel(const float* __restrict__ kpar, int l) {
    __shared__ float accw[CS][17];
    __shared__ float smag[CS];
    int b = blockIdx.x, ch = blockIdx.y;
    int d = threadIdx.x;
    int lane = d & 31, wid = d >> 5;
    int t0 = ch * CS;
    size_t base = ((size_t)b * TT + t0) * DD + d;
    float acc = g_partA[((size_t)b * NCH + ch) * DD + d];
    float hp = (t0 > 0) ? g_h[base - DD] : 0.f;
    #pragma unroll 4
    for (int i = 0; i < CS; i++) {
        float v = g_h[base + (size_t)i * DD];
        acc += v;
        float diff = acc - hp;
        float sq = diff * diff;
        #pragma unroll
        for (int o = 16; o; o >>= 1) sq += __shfl_down_sync(0xffffffffu, sq, o);
        if (lane == 0) accw[i][wid] = sq;
        hp = v;
    }
    __syncthreads();
    if (d < CS) {
        float s = 0.f;
        #pragma unroll
        for (int w = 0; w < 16; w++) s += accw[d][w];
        smag[d] = sqrtf(s);
    }
    __syncthreads();
    float lam = softplus_lambda(kpar[l]);
    float S = g_partB[((size_t)b * NCH + ch) * DD + d];
    #pragma unroll 4
    for (int i = 0; i < CS; i++) {
        size_t idx = base + (size_t)i * DD;
        S = g_h[idx] + lam * S;
        g_s1[idx] = fabsf(smag[i] * S);
    }
}

// ---------------- block reduction ----------------
__device__ __forceinline__ float block_reduce(float v, float* sh) {
    int lane = threadIdx.x & 31, wid = threadIdx.x >> 5;
    #pragma unroll
    for (int o = 16; o; o >>= 1) v += __shfl_down_sync(0xffffffffu, v, o);
    if (lane == 0) sh[wid] = v;
    __syncthreads();
    float r = 0.f;
    if (threadIdx.x < (blockDim.x >> 5)) r = sh[threadIdx.x];
    if (wid == 0) {
        #pragma unroll
        for (int o = 16; o; o >>= 1) r += __shfl_down_sync(0xffffffffu, r, o);
        if (lane == 0) sh[0] = r;
    }
    __syncthreads();
    r = sh[0];
    __syncthreads();
    return r;
}

// ---------------- layernorm -> pre-split bf16 s2 ----------------
__global__ void layernorm_kernel(const float* __restrict__ gamma, const float* __restrict__ beta) {
    __shared__ float row[DD];
    __shared__ float sh[32];
    int tok = blockIdx.x;
    size_t base = (size_t)tok * DD;
    float s = 0.f;
    for (int d = threadIdx.x; d < DD; d += blockDim.x) {
        float v = g_s1[base + d];
        row[d] = v;
        s += v;
    }
    s = block_reduce(s, sh);
    float mu = s * (1.0f / DD);
    float q = 0.f;
    for (int d = threadIdx.x; d < DD; d += blockDim.x) {
        float v = row[d] - mu;
        q += v * v;
    }
    q = block_reduce(q, sh);
    float rstd = rsqrtf(q * (1.0f / DD) + 1e-3f);
    for (int d = threadIdx.x; d < DD; d += blockDim.x) {
        float y = (row[d] - mu) * rstd * gamma[d] + beta[d];
        __nv_bfloat16 h = __float2bfloat16(y);
        g_s2h[base + d] = h;
        g_s2l[base + d] = __float2bfloat16(y - __bfloat162float(h));
    }
}

// ================= bf16x3 tensor-core GEMM (ldmatrix + m16n8k16) ===========
// EXACT R4 version (proven correct): block 128x256x16, 8 warps, double buffer.
#define AROWB 48
#define A_TILE_B (128*AROWB)           // 6144
#define BROWB 528
#define B_TILE_B (16*BROWB)            // 8448
#define SM_A_BYTES (4*A_TILE_B)
#define SM_B_BYTES (4*B_TILE_B)
#define GSMEM (SM_A_BYTES + SM_B_BYTES)  // 58368

#define LDSM4(r0,r1,r2,r3,addr) \
    asm volatile("ldmatrix.sync.aligned.m8n8.x4.shared.b16 {%0,%1,%2,%3},[%4];" \
                 : "=r"(r0),"=r"(r1),"=r"(r2),"=r"(r3) : "r"(addr))
#define LDSM4T(r0,r1,r2,r3,addr) \
    asm volatile("ldmatrix.sync.aligned.m8n8.x4.trans.shared.b16 {%0,%1,%2,%3},[%4];" \
                 : "=r"(r0),"=r"(r1),"=r"(r2),"=r"(r3) : "r"(addr))
#define MMA_BF16(c,a,b0,b1) \
    asm volatile("mma.sync.aligned.m16n8k16.row.col.f32.bf16.bf16.f32 " \
                 "{%0,%1,%2,%3},{%4,%5,%6,%7},{%8,%9},{%0,%1,%2,%3};" \
                 : "+f"(c[0]),"+f"(c[1]),"+f"(c[2]),"+f"(c[3]) \
                 : "r"(a[0]),"r"(a[1]),"r"(a[2]),"r"(a[3]),"r"(b0),"r"(b1))

struct StageRegs { uint4 ah, al, bh0, bh1, bl0, bl1; };

__device__ __forceinline__ void ldg_tile(const __nv_bfloat16* __restrict__ Ah,
                                         const __nv_bfloat16* __restrict__ Al,
                                         const __nv_bfloat16* __restrict__ Bh,
                                         const __nv_bfloat16* __restrict__ Bl,
                                         int bm, int bn, int k0, int K, int N,
                                         int tid, StageRegs& r) {
    int arow = tid >> 1, aseg = tid & 1;
    size_t abase = (size_t)(bm + arow) * K + k0 + aseg * 8;
    r.ah = *(const uint4*)(Ah + abase);
    r.al = *(const uint4*)(Al + abase);
    int k = tid >> 5, ng = tid & 31;
    size_t bbase0 = (size_t)(k0 + k) * N + bn + ng * 8;
    size_t bbase1 = (size_t)(k0 + k + 8) * N + bn + ng * 8;
    r.bh0 = *(const uint4*)(Bh + bbase0);
    r.bh1 = *(const uint4*)(Bh + bbase1);
    r.bl0 = *(const uint4*)(Bl + bbase0);
    r.bl1 = *(const uint4*)(Bl + bbase1);
}

__device__ __forceinline__ void sts_tile(char* sbase, int p, int tid, const StageRegs& r) {
    int arow = tid >> 1, aseg = tid & 1;
    char* A = sbase + p * (2 * A_TILE_B);
    *(uint4*)(A + arow * AROWB + aseg * 16) = r.ah;
    *(uint4*)(A + A_TILE_B + arow * AROWB + aseg * 16) = r.al;
    int k = tid >> 5, ng = tid & 31;
    char* Bp = sbase + SM_A_BYTES + p * (2 * B_TILE_B);
    *(uint4*)(Bp + k * BROWB + ng * 16) = r.bh0;
    *(uint4*)(Bp + (k + 8) * BROWB + ng * 16) = r.bh1;
    *(uint4*)(Bp + B_TILE_B + k * BROWB + ng * 16) = r.bl0;
    *(uint4*)(Bp + B_TILE_B + (k + 8) * BROWB + ng * 16) = r.bl1;
}

__device__ __forceinline__ float gelu_exact(float c) {
    return 0.5f * c * (1.0f + erff(c * 0.70710678118654752f));
}

template <int EPI>
__device__ __forceinline__ void gemm_bf16x3(const __nv_bfloat16* __restrict__ Ah,
                                            const __nv_bfloat16* __restrict__ Al,
                                            const __nv_bfloat16* __restrict__ Bh,
                                            const __nv_bfloat16* __restrict__ Bl,
                                            const float* __restrict__ bias,
                                            float* __restrict__ Cf,
                                            __nv_bfloat16* __restrict__ Ch,
                                            __nv_bfloat16* __restrict__ Cl,
                                            int M, int N, int K) {
    extern __shared__ char smc[];
    const int bm = blockIdx.y * 128;
    const int bn = blockIdx.x * 256;
    const int tid = threadIdx.x;
    const int lane = tid & 31;
    const int wid = tid >> 5;
    const int wm = wid >> 2, wn = wid & 3;
    const int g = lane >> 2, kq = lane & 3;
    const int lrow = lane & 7, lmat = lane >> 3;

    const uint32_t smem_u32 = (uint32_t)__cvta_generic_to_shared(smc);
    const uint32_t aoff = smem_u32 + (uint32_t)((wm * 64 + (lmat & 1) * 8 + lrow) * AROWB + (lmat >> 1) * 16);
    const uint32_t boff = smem_u32 + SM_A_BYTES +
                          (uint32_t)(((lmat & 1) * 8 + lrow) * BROWB + (wn * 64 + (lmat >> 1) * 8) * 2);

    float acc[4][8][4];
    #pragma unroll
    for (int mt = 0; mt < 4; mt++)
        #pragma unroll
        for (int nt = 0; nt < 8; nt++)
            #pragma unroll
            for (int r = 0; r < 4; r++) acc[mt][nt][r] = 0.f;

    const int KT = K >> 4;
    StageRegs sr;
    ldg_tile(Ah, Al, Bh, Bl, bm, bn, 0, K, N, tid, sr);
    sts_tile(smc, 0, tid, sr);
    __syncthreads();

    for (int kt = 0; kt < KT; kt++) {
        const int p = kt & 1;
        const bool more = (kt + 1 < KT);
        if (more) ldg_tile(Ah, Al, Bh, Bl, bm, bn, (kt + 1) << 4, K, N, tid, sr);

        const uint32_t aB = aoff + p * (2 * A_TILE_B);
        const uint32_t bB = boff + p * (2 * B_TILE_B);
        uint32_t aH[4][4], aL[4][4];
        #pragma unroll
        for (int mt = 0; mt < 4; mt++) {
            LDSM4(aH[mt][0], aH[mt][1], aH[mt][2], aH[mt][3], aB + mt * (16 * AROWB));
            LDSM4(aL[mt][0], aL[mt][1], aL[mt][2], aL[mt][3], aB + mt * (16 * AROWB) + A_TILE_B);
        }
        #pragma unroll
        for (int ntp = 0; ntp < 4; ntp++) {
            uint32_t bh[4], bl[4];
            LDSM4T(bh[0], bh[1], bh[2], bh[3], bB + ntp * 32);
            LDSM4T(bl[0], bl[1], bl[2], bl[3], bB + ntp * 32 + B_TILE_B);
            #pragma unroll
            for (int w = 0; w < 2; w++) {
                const int nt = 2 * ntp + w;
                #pragma unroll
                for (int mt = 0; mt < 4; mt++) {
                    MMA_BF16(acc[mt][nt], aL[mt], bh[2 * w], bh[2 * w + 1]);
                    MMA_BF16(acc[mt][nt], aH[mt], bl[2 * w], bl[2 * w + 1]);
                    MMA_BF16(acc[mt][nt], aH[mt], bh[2 * w], bh[2 * w + 1]);
                }
            }
        }
        if (more) sts_tile(smc, p ^ 1, tid, sr);
        __syncthreads();
    }

    // epilogue
    #pragma unroll
    for (int mt = 0; mt < 4; mt++) {
        const int m0 = bm + wm * 64 + mt * 16 + g;
        #pragma unroll
        for (int nt = 0; nt < 8; nt++) {
            const int n0 = bn + wn * 64 + nt * 8 + kq * 2;
            const float b0 = bias[n0], b1 = bias[n0 + 1];
            if (EPI == 0) {
                float v0 = gelu_exact(acc[mt][nt][0] + b0);
                float v1 = gelu_exact(acc[mt][nt][1] + b1);
                float v2 = gelu_exact(acc[mt][nt][2] + b0);
                float v3 = gelu_exact(acc[mt][nt][3] + b1);
                __nv_bfloat16 h0 = __float2bfloat16(v0), h1 = __float2bfloat16(v1);
                __nv_bfloat16 h2 = __float2bfloat16(v2), h3 = __float2bfloat16(v3);
                uint32_t hw0 = (uint32_t)__bfloat16_as_ushort(h0) | ((uint32_t)__bfloat16_as_ushort(h1) << 16);
                uint32_t hw1 = (uint32_t)__bfloat16_as_ushort(h2) | ((uint32_t)__bfloat16_as_ushort(h3) << 16);
                __nv_bfloat16 l0 = __float2bfloat16(v0 - __bfloat162float(h0));
                __nv_bfloat16 l1 = __float2bfloat16(v1 - __bfloat162float(h1));
                __nv_bfloat16 l2 = __float2bfloat16(v2 - __bfloat162float(h2));
                __nv_bfloat16 l3 = __float2bfloat16(v3 - __bfloat162float(h3));
                uint32_t lw0 = (uint32_t)__bfloat16_as_ushort(l0) | ((uint32_t)__bfloat16_as_ushort(l1) << 16);
                uint32_t lw1 = (uint32_t)__bfloat16_as_ushort(l2) | ((uint32_t)__bfloat16_as_ushort(l3) << 16);
                size_t i0 = ((size_t)m0 * N + n0) >> 1;
                size_t i1 = ((size_t)(m0 + 8) * N + n0) >> 1;
                ((uint32_t*)Ch)[i0] = hw0;
                ((uint32_t*)Cl)[i0] = lw0;
                ((uint32_t*)Ch)[i1] = hw1;
                ((uint32_t*)Cl)[i1] = lw1;
            } else {
                float2* p0 = (float2*)&Cf[(size_t)m0 * N + n0];
                float2* p1 = (float2*)&Cf[(size_t)(m0 + 8) * N + n0];
                float2 o0 = *p0, o1 = *p1;
                o0.x += acc[mt][nt][0] + b0;
                o0.y += acc[mt][nt][1] + b1;
                o1.x += acc[mt][nt][2] + b0;
                o1.y += acc[mt][nt][3] + b1;
                *p0 = o0;
                *p1 = o1;
            }
        }
    }
}

__global__ void __launch_bounds__(256, 1) gemm1_bf16(const float* __restrict__ b1, int l) {
    gemm_bf16x3<0>(g_s2h, g_s2l, g_w1h + (size_t)l * DD * HH, g_w1l + (size_t)l * DD * HH,
                   b1, nullptr, g_acth, g_actl, NTOK, HH, DD);
}
__global__ void __launch_bounds__(256, 1) gemm2_bf16(const float* __restrict__ b2, int l) {
    gemm_bf16x3<1>(g_acth, g_actl, g_w2h + (size_t)l * DD * HH, g_w2l + (size_t)l * DD * HH,
                   b2, g_h, nullptr, nullptr, NTOK, DD, HH);
}

// ---------------- fp32 SGEMM for output projection --------------------------
__global__ void __launch_bounds__(256) gemm_out_kernel(const float* __restrict__ embed,
                                                       float* __restrict__ out) {
    __shared__ float As[16][128];
    __shared__ float Bs[16][132];
    const float* A = g_h;
    const float* B = embed;
    const int N = VV, K = DD;
    const int bm = blockIdx.y * 128, bn = blockIdx.x * 128;
    const int tid = threadIdx.x;
    const int ty = tid >> 4, tx = tid & 15;
    float acc[8][8];
    #pragma unroll
    for (int i = 0; i < 8; i++)
        #pragma unroll
        for (int j = 0; j < 8; j++) acc[i][j] = 0.f;

    for (int k0 = 0; k0 < K; k0 += 16) {
        #pragma unroll
        for (int r = 0; r < 2; r++) {
            int slot = tid + r * 256;
            int arow = slot >> 2;
            int ac = (slot & 3) << 2;
            const float4 v = *(const float4*)(A + (size_t)(bm + arow) * K + k0 + ac);
            As[ac + 0][arow] = v.x;
            As[ac + 1][arow] = v.y;
            As[ac + 2][arow] = v.z;
            As[ac + 3][arow] = v.w;
        }
        #pragma unroll
        for (int r = 0; r < 2; r++) {
            int slot = tid + r * 256;
            int nr = slot >> 2;
            int kc = (slot & 3) << 2;
            const float4 v = *(const float4*)(B + (size_t)(bn + nr) * K + k0 + kc);
            Bs[kc + 0][nr] = v.x;
            Bs[kc + 1][nr] = v.y;
            Bs[kc + 2][nr] = v.z;
            Bs[kc + 3][nr] = v.w;
        }
        __syncthreads();
        #pragma unroll
        for (int kk = 0; kk < 16; kk++) {
            float ra[8], rb[8];
            *(float4*)&ra[0] = *(const float4*)&As[kk][ty * 8];
            *(float4*)&ra[4] = *(const float4*)&As[kk][ty * 8 + 4];
            *(float4*)&rb[0] = *(const float4*)&Bs[kk][tx * 8];
            *(float4*)&rb[4] = *(const float4*)&Bs[kk][tx * 8 + 4];
            #pragma unroll
            for (int i = 0; i < 8; i++)
                #pragma unroll
                for (int j = 0; j < 8; j++) acc[i][j] += ra[i] * rb[j];
        }
        __syncthreads();
    }

    int row0 = bm + ty * 8, col0 = bn + tx * 8;
    #pragma unroll
    for (int i = 0; i < 8; i++)
        #pragma unroll
        for (int j = 0; j < 8; j++)
            out[(size_t)(row0 + i) * N + col0 + j] = acc[i][j];
}

// ---------------- launcher ----------------
extern "C" void kernel_launch(void* const* d_in, const int* in_sizes, int n_in,
                              void* d_out, int out_size) {
    const int*   x     = (const int*)d_in[0];
    const float* embed = (const float*)d_in[1];
    const float* kpar  = (const float*)d_in[2];
    const float* gamma = (const float*)d_in[3];
    const float* beta  = (const float*)d_in[4];
    const float* W1    = (const float*)d_in[5];
    const float* b1    = (const float*)d_in[6];
    const float* W2    = (const float*)d_in[7];
    const float* b2    = (const float*)d_in[8];
    float* out = (float*)d_out;

    cudaFuncSetAttribute(gemm1_bf16, cudaFuncAttributeMaxDynamicSharedMemorySize, GSMEM);
    cudaFuncSetAttribute(gemm2_bf16, cudaFuncAttributeMaxDynamicSharedMemorySize, GSMEM);

    dim3 sg(BB, NCH);

    embed_cumprod_kernel<<<NTOK / 8, 256>>>(x, embed);
    split_weights_kernel<<<(3 * DD * HH) / 256, 256>>>(W1, W2);
    boundA_kernel<<<sg, DD>>>();
    boundB_kernel<<<BB, DD>>>();
    boundC_kernel<<<sg, DD>>>();

    for (int l = 0; l < 3; l++) {
        scanA_kernel<<<sg, DD>>>(kpar, l);
        scanB_kernel<<<BB, DD>>>(kpar, l);
        magdecayC_kernel<<<sg, DD>>>(kpar, l);
        layernorm_kernel<<<NTOK, 128>>>(gamma + l * DD, beta + l * DD);
        gemm1_bf16<<<dim3(HH / 256, NTOK / 128), 256, GSMEM>>>(b1 + l * HH, l);
        gemm2_bf16<<<dim3(DD / 256, NTOK / 128), 256, GSMEM>>>(b2 + l * DD, l);
    }
    gemm_out_kernel<<<dim3(VV / 128, NTOK / 128), 256>>>(embed, out);
}